// round 2
// baseline (speedup 1.0000x reference)
#include <cuda_runtime.h>
#include <math.h>

#define U_N 50000
#define B_N 20000
#define I_N 100000
#define D 64
#define BATCH 2048
#define INVTAU 4.0f
#define LAM1 0.04f
#define LAM2 1e-5f
#define XI (1.0f/3.0f)

// ---------------- static device workspace (no allocs allowed) ----------------
__device__ float g_feats[(U_N + I_N) * D];   // max n = U+I = 150000
__device__ float g_tmp  [(U_N + I_N) * D];
__device__ float g_UB   [(U_N + B_N) * D];
__device__ float g_UI   [(U_N + I_N) * D];
__device__ float g_BI   [(B_N + I_N) * D];
__device__ float g_UIb  [B_N * D];           // aggregated UI_b
__device__ float g_BIu  [U_N * D];           // aggregated BI_u
__device__ float g_P    [6 * D * BATCH];     // normalized CL matrices, k-major: [p][k][i]
__device__ float g_acc  [4];                 // 0: sum logsigmoid, 1: reg, 2: cl

__constant__ int c_pa[12] = {0,0,1,3,3,4, 0,1,2,3,4,5};
__constant__ int c_pb[12] = {1,2,2,4,5,5, 0,1,2,3,4,5};

// ---------------- small helpers ----------------
__device__ __forceinline__ float warp_sum(float v) {
#pragma unroll
    for (int o = 16; o; o >>= 1) v += __shfl_xor_sync(0xffffffffu, v, o);
    return v;
}
__device__ __forceinline__ float sgn(float x) {
    return (x > 0.f) ? 1.f : ((x < 0.f) ? -1.f : 0.f);
}
__device__ __forceinline__ void red4(float* p, float4 o) {
    asm volatile("red.global.add.v4.f32 [%0], {%1,%2,%3,%4};"
                 :: "l"(p), "f"(o.x), "f"(o.y), "f"(o.z), "f"(o.w) : "memory");
}

// ---------------- kernels ----------------

// feats = concat(A, Bf); outb = feats * xi (layer-0 term is RAW, un-normalized)
__global__ void k_init(const float* __restrict__ A, const float* __restrict__ Bf,
                       int nA, int n, float* feats, float* outb) {
    int i = blockIdx.x * blockDim.x + threadIdx.x;
    if (i >= n * D) return;
    float v = (i < nA * D) ? A[i] : Bf[i - nA * D];
    feats[i] = v;
    outb[i]  = v * XI;
}

// out[rows[e]] += vals[e] * x[cols[e]]
// 4 threads per edge, each handles 4 contiguous float4 (64B). MLP=4 per thread.
__global__ void k_spmm(const int* __restrict__ rows, const int* __restrict__ cols,
                       const float* __restrict__ vals, const float* __restrict__ x,
                       float* out, int nE) {
    int t = blockIdx.x * blockDim.x + threadIdx.x;
    int e = t >> 2;
    if (e >= nE) return;
    int q = t & 3;                         // 64B chunk within the row
    int r  = __ldg(rows + e);
    int cc = __ldg(cols + e);
    float v = __ldg(vals + e);
    const float4* xp = (const float4*)(x + (size_t)cc * D) + q * 4;
    float4 a0 = __ldg(xp + 0);
    float4 a1 = __ldg(xp + 1);
    float4 a2 = __ldg(xp + 2);
    float4 a3 = __ldg(xp + 3);
    float* p = out + (size_t)r * D + q * 16;
    red4(p +  0, make_float4(v*a0.x, v*a0.y, v*a0.z, v*a0.w));
    red4(p +  4, make_float4(v*a1.x, v*a1.y, v*a1.z, v*a1.w));
    red4(p +  8, make_float4(v*a2.x, v*a2.y, v*a2.z, v*a2.w));
    red4(p + 12, make_float4(v*a3.x, v*a3.y, v*a3.z, v*a3.w));
}

// per-row: f = tmp + sign(tmp)*l2norm(noise)*ups ; outb += xi*l2norm(f) ; feats = f
__global__ void k_prop_row(const float* __restrict__ tmp, const float* __restrict__ noise,
                           float* feats, float* outb, int n, float ups) {
    int row = blockIdx.x * 8 + (threadIdx.x >> 5);
    int lane = threadIdx.x & 31;
    if (row >= n) return;
    size_t off = (size_t)row * D + lane * 2;
    float2 t  = *(const float2*)(tmp + off);
    float2 nz = *(const float2*)(noise + off);
    float ns = warp_sum(nz.x * nz.x + nz.y * nz.y);
    float ninv = ups / fmaxf(sqrtf(ns), 1e-12f);
    float fx = t.x + sgn(t.x) * nz.x * ninv;
    float fy = t.y + sgn(t.y) * nz.y * ninv;
    float fs = warp_sum(fx * fx + fy * fy);
    float finv = XI / fmaxf(sqrtf(fs), 1e-12f);
    float2 ob = *(float2*)(outb + off);
    ob.x += fx * finv;
    ob.y += fy * finv;
    *(float2*)(outb + off) = ob;
    *(float2*)(feats + off) = make_float2(fx, fy);
}

// aggregate: out = agg + sign(agg)*l2norm(noise)*ups (no normalize, overwrite)
__global__ void k_agg_row(const float* __restrict__ tmp, const float* __restrict__ noise,
                          float* outb, int n, float ups) {
    int row = blockIdx.x * 8 + (threadIdx.x >> 5);
    int lane = threadIdx.x & 31;
    if (row >= n) return;
    size_t off = (size_t)row * D + lane * 2;
    float2 t  = *(const float2*)(tmp + off);
    float2 nz = *(const float2*)(noise + off);
    float ns = warp_sum(nz.x * nz.x + nz.y * nz.y);
    float ninv = ups / fmaxf(sqrtf(ns), 1e-12f);
    float fx = t.x + sgn(t.x) * nz.x * ninv;
    float fy = t.y + sgn(t.y) * nz.y * ninv;
    *(float2*)(outb + off) = make_float2(fx, fy);
}

__global__ void k_sumsq(const float* __restrict__ x, int n, float* acc) {
    float s = 0.f;
    for (int i = blockIdx.x * blockDim.x + threadIdx.x; i < n; i += gridDim.x * blockDim.x) {
        float v = x[i];
        s += v * v;
    }
    s = warp_sum(s);
    __shared__ float sm[8];
    if ((threadIdx.x & 31) == 0) sm[threadIdx.x >> 5] = s;
    __syncthreads();
    if (threadIdx.x == 0) {
        float tt = 0.f;
#pragma unroll
        for (int i = 0; i < 8; ++i) tt += sm[i];
        atomicAdd(acc, tt);
    }
}

// BPR: warp per batch row; reps built on the fly
__global__ void k_bpr(const int* __restrict__ users, const int* __restrict__ bundles,
                      const float* __restrict__ UIu, const float* __restrict__ BIu,
                      const float* __restrict__ UIb, const float* __restrict__ BIb,
                      float* acc) {
    int i = blockIdx.x * 8 + (threadIdx.x >> 5);
    int lane = threadIdx.x & 31;
    if (i >= BATCH) return;
    int u  = users[i];
    int bp = bundles[2 * i];
    int bn = bundles[2 * i + 1];
    size_t uo = (size_t)u * D + lane * 2;
    float2 a1 = *(const float2*)(UIu + uo);
    float2 a2 = *(const float2*)(BIu + uo);
    float ux = 0.5f * (a1.x + a2.x), uy = 0.5f * (a1.y + a2.y);
    size_t po = (size_t)bp * D + lane * 2;
    float2 p1 = *(const float2*)(UIb + po);
    float2 p2 = *(const float2*)(BIb + po);
    float px = 0.5f * (p1.x + p2.x), py = 0.5f * (p1.y + p2.y);
    size_t no = (size_t)bn * D + lane * 2;
    float2 q1 = *(const float2*)(UIb + no);
    float2 q2 = *(const float2*)(BIb + no);
    float qx = 0.5f * (q1.x + q2.x), qy = 0.5f * (q1.y + q2.y);
    float dp = warp_sum(ux * px + uy * py);
    float dn = warp_sum(ux * qx + uy * qy);
    if (lane == 0) {
        float x = dp - dn;
        float ls = (x >= 0.f) ? -log1pf(expf(-x)) : (x - log1pf(expf(x)));
        atomicAdd(acc, ls);
    }
}

// gather + row-normalize the 6 CL matrices into k-major layout g_P[p][k][i]
__global__ void k_gather(const int* __restrict__ users, const int* __restrict__ bundles,
                         const float* __restrict__ UB, const float* __restrict__ UI,
                         const float* __restrict__ BIu, const float* __restrict__ UIb,
                         const float* __restrict__ BI, float* P) {
    int i = blockIdx.x * 8 + (threadIdx.x >> 5);
    int lane = threadIdx.x & 31;
    int p = blockIdx.y;
    if (i >= BATCH) return;
    int u0 = users[i];
    int b0 = bundles[2 * i];
    const float* src;
    switch (p) {
        case 0:  src = UB  + (size_t)u0 * D; break;
        case 1:  src = UI  + (size_t)u0 * D; break;
        case 2:  src = BIu + (size_t)u0 * D; break;
        case 3:  src = UB  + (size_t)(U_N + b0) * D; break;
        case 4:  src = UIb + (size_t)b0 * D; break;
        default: src = BI  + (size_t)b0 * D; break;
    }
    float2 v = *(const float2*)(src + lane * 2);
    float s = warp_sum(v.x * v.x + v.y * v.y);
    float inv = 1.f / fmaxf(sqrtf(s), 1e-12f);
    float* dst = P + ((size_t)p * D) * BATCH + i;
    dst[(size_t)(2 * lane) * BATCH]     = v.x * inv;
    dst[(size_t)(2 * lane + 1) * BATCH] = v.y * inv;
}

// 12 contrastive losses: S = P@Q^T/tau (2048x2048, K=64), loss_i = log(sum_j exp(S_ij)) - S_ii
// tile: 64 i-rows x 128 j-rows, 256 threads, per-thread 4x8 register tile, k-major smem.
__global__ void __launch_bounds__(256) k_cl(const float* __restrict__ P, float* acc) {
    __shared__ float Ps[64 * 64];    // [k][i] 16KB
    __shared__ float Qs[64 * 128];   // [k][j] 32KB
    int p  = blockIdx.y;
    int bi = blockIdx.x;
    int tid = threadIdx.x;
    int tx = tid & 15;     // j sub-tile (8 cols each)
    int ty = tid >> 4;     // i sub-tile (4 rows each)
    const float* Pg = P + (size_t)c_pa[p] * D * BATCH;
    const float* Qg = P + (size_t)c_pb[p] * D * BATCH;
    for (int idx = tid; idx < 64 * 16; idx += 256) {
        int k = idx >> 4, c4 = idx & 15;
        *(float4*)(Ps + k * 64 + c4 * 4) = *(const float4*)(Pg + (size_t)k * BATCH + bi * 64 + c4 * 4);
    }
    float rs[4] = {0.f, 0.f, 0.f, 0.f};
    float sii[4] = {0.f, 0.f, 0.f, 0.f};
    int ibase = bi * 64 + ty * 4;
    for (int jt = 0; jt < 16; ++jt) {
        __syncthreads();
        for (int idx = tid; idx < 64 * 32; idx += 256) {
            int k = idx >> 5, c4 = idx & 31;
            *(float4*)(Qs + k * 128 + c4 * 4) = *(const float4*)(Qg + (size_t)k * BATCH + jt * 128 + c4 * 4);
        }
        __syncthreads();
        float av[4][8];
#pragma unroll
        for (int r = 0; r < 4; ++r)
#pragma unroll
            for (int c = 0; c < 8; ++c) av[r][c] = 0.f;
#pragma unroll 8
        for (int k = 0; k < 64; ++k) {
            float a[4], b[8];
            *(float4*)a       = *(const float4*)(Ps + k * 64 + ty * 4);
            *(float4*)b       = *(const float4*)(Qs + k * 128 + tx * 8);
            *(float4*)(b + 4) = *(const float4*)(Qs + k * 128 + tx * 8 + 4);
#pragma unroll
            for (int r = 0; r < 4; ++r)
#pragma unroll
                for (int c = 0; c < 8; ++c) av[r][c] += a[r] * b[c];
        }
        int jbase = jt * 128 + tx * 8;
#pragma unroll
        for (int r = 0; r < 4; ++r) {
#pragma unroll
            for (int c = 0; c < 8; ++c) {
                float s = av[r][c] * INVTAU;
                if (jbase + c == ibase + r) sii[r] = s;
                rs[r] += __expf(s);
            }
        }
    }
    // reduce row-sums across tx (lanes share ty within 16-lane half-warps)
#pragma unroll
    for (int r = 0; r < 4; ++r)
#pragma unroll
        for (int o = 1; o < 16; o <<= 1) rs[r] += __shfl_xor_sync(0xffffffffu, rs[r], o);
    // fetch each row's diagonal from the lane that computed it
    float part = 0.f;
#pragma unroll
    for (int r = 0; r < 4; ++r) {
        int ig = ibase + r;
        int tx_d = (ig & 127) >> 3;
        int srcLane = ((ty & 1) << 4) | tx_d;
        float s = __shfl_sync(0xffffffffu, sii[r], srcLane);
        if (tx == 0) part += logf(rs[r]) - s;
    }
    if (tx == 0) atomicAdd(acc, (LAM1 * 0.5f / (float)BATCH) * part);
}

__global__ void k_final(const float* __restrict__ acc, float* out, int out_size) {
    if (threadIdx.x == 0) {
        out[0] = -acc[0] / (float)BATCH + LAM2 * acc[1];
        if (out_size > 1) out[1] = acc[2];
    }
}

// ---------------- host orchestration ----------------
extern "C" void kernel_launch(void* const* d_in, const int* in_sizes, int n_in,
                              void* d_out, int out_size) {
    const float* uf  = (const float*)d_in[0];
    const float* bfe = (const float*)d_in[1];
    const float* itf = (const float*)d_in[2];
    const int*   ub_r = (const int*)d_in[3];
    const int*   ub_c = (const int*)d_in[4];
    const float* ub_v = (const float*)d_in[5];
    const int*   ui_r = (const int*)d_in[6];
    const int*   ui_c = (const int*)d_in[7];
    const float* ui_v = (const float*)d_in[8];
    const int*   bi_r = (const int*)d_in[9];
    const int*   bi_c = (const int*)d_in[10];
    const float* bi_v = (const float*)d_in[11];
    const int*   ba_r = (const int*)d_in[12];
    const int*   ba_c = (const int*)d_in[13];
    const float* ba_v = (const float*)d_in[14];
    const int*   ua_r = (const int*)d_in[15];
    const int*   ua_c = (const int*)d_in[16];
    const float* ua_v = (const float*)d_in[17];
    const float* n_UB  = (const float*)d_in[18];
    const float* n_UI  = (const float*)d_in[19];
    const float* n_BI  = (const float*)d_in[20];
    const float* n_aBI = (const float*)d_in[21];
    const float* n_aUI = (const float*)d_in[22];
    const int* users   = (const int*)d_in[23];
    const int* bundles = (const int*)d_in[24];

    int nUB = in_sizes[3];
    int nUI = in_sizes[6];
    int nBI = in_sizes[9];
    int nBA = in_sizes[12];
    int nUA = in_sizes[15];

    float *feats, *tmp, *pUB, *pUI, *pBI, *pUIb, *pBIu, *pP, *acc;
    cudaGetSymbolAddress((void**)&feats, g_feats);
    cudaGetSymbolAddress((void**)&tmp,   g_tmp);
    cudaGetSymbolAddress((void**)&pUB,   g_UB);
    cudaGetSymbolAddress((void**)&pUI,   g_UI);
    cudaGetSymbolAddress((void**)&pBI,   g_BI);
    cudaGetSymbolAddress((void**)&pUIb,  g_UIb);
    cudaGetSymbolAddress((void**)&pBIu,  g_BIu);
    cudaGetSymbolAddress((void**)&pP,    g_P);
    cudaGetSymbolAddress((void**)&acc,   g_acc);

    cudaMemsetAsync(acc, 0, 4 * sizeof(float), 0);

    auto propagate = [&](const int* r, const int* c, const float* v, int nE,
                         const float* A, const float* Bf, int nA, int n,
                         const float* noise, float ups, float* outb) {
        int nd = n * D;
        k_init<<<(nd + 255) / 256, 256>>>(A, Bf, nA, n, feats, outb);
        for (int l = 0; l < 2; ++l) {
            cudaMemsetAsync(tmp, 0, (size_t)nd * sizeof(float), 0);
            int thr = nE * 4;
            k_spmm<<<(thr + 255) / 256, 256>>>(r, c, v, feats, tmp, nE);
            k_prop_row<<<(n + 7) / 8, 256>>>(tmp, noise + (size_t)l * nd, feats, outb, n, ups);
        }
    };

    propagate(ub_r, ub_c, ub_v, nUB, uf,  bfe, U_N, U_N + B_N, n_UB, 0.1f, pUB);
    propagate(ui_r, ui_c, ui_v, nUI, uf,  itf, U_N, U_N + I_N, n_UI, 0.1f, pUI);
    propagate(bi_r, bi_c, bi_v, nBI, bfe, itf, B_N, B_N + I_N, n_BI, 0.1f, pBI);

    // UI_b = aggregate(biagg, UI_i)  -> B rows
    {
        cudaMemsetAsync(tmp, 0, (size_t)B_N * D * sizeof(float), 0);
        int thr = nBA * 4;
        k_spmm<<<(thr + 255) / 256, 256>>>(ba_r, ba_c, ba_v, pUI + (size_t)U_N * D, tmp, nBA);
        k_agg_row<<<(B_N + 7) / 8, 256>>>(tmp, n_aBI, pUIb, B_N, 0.1f);
    }
    // BI_u = aggregate(uiagg, BI_i)  -> U rows
    {
        cudaMemsetAsync(tmp, 0, (size_t)U_N * D * sizeof(float), 0);
        int thr = nUA * 4;
        k_spmm<<<(thr + 255) / 256, 256>>>(ua_r, ua_c, ua_v, pBI + (size_t)B_N * D, tmp, nUA);
        k_agg_row<<<(U_N + 7) / 8, 256>>>(tmp, n_aUI, pBIu, U_N, 0.1f);
    }

    // regularizer
    k_sumsq<<<592, 256>>>(uf,  U_N * D, acc + 1);
    k_sumsq<<<592, 256>>>(bfe, B_N * D, acc + 1);
    k_sumsq<<<592, 256>>>(itf, I_N * D, acc + 1);

    // BPR
    k_bpr<<<(BATCH + 7) / 8, 256>>>(users, bundles, pUI, pBIu, pUIb, pBI, acc);

    // CL matrices + losses
    dim3 gg((BATCH + 7) / 8, 6);
    k_gather<<<gg, 256>>>(users, bundles, pUB, pUI, pBIu, pUIb, pBI, pP);
    k_cl<<<dim3(32, 12), 256>>>(pP, acc + 2);

    k_final<<<1, 1>>>(acc, (float*)d_out, out_size);
}

// round 3
// speedup vs baseline: 1.3324x; 1.3324x over previous
#include <cuda_runtime.h>
#include <math.h>

#define U_N 50000
#define B_N 20000
#define I_N 100000
#define D 64
#define BATCH 2048
#define INVTAU 4.0f
#define LAM1 0.04f
#define LAM2 1e-5f
#define XI (1.0f/3.0f)

// ---------------- static device workspace (no allocs allowed) ----------------
__device__ float g_feats[(U_N + I_N) * D];   // max n = U+I = 150000
__device__ float g_tmp  [(U_N + I_N) * D];
__device__ float g_UB   [(U_N + B_N) * D];
__device__ float g_UI   [(U_N + I_N) * D];
__device__ float g_BI   [(B_N + I_N) * D];
__device__ float g_UIb  [B_N * D];           // aggregated UI_b
__device__ float g_BIu  [U_N * D];           // aggregated BI_u
__device__ float g_P    [6 * D * BATCH];     // normalized CL matrices, k-major: [p][k][i]
__device__ float g_acc  [4];                 // 0: sum logsigmoid, 1: reg, 2: cl

__constant__ int c_pa[12] = {0,0,1,3,3,4, 0,1,2,3,4,5};
__constant__ int c_pb[12] = {1,2,2,4,5,5, 0,1,2,3,4,5};

// ---------------- small helpers ----------------
__device__ __forceinline__ float warp_sum(float v) {
#pragma unroll
    for (int o = 16; o; o >>= 1) v += __shfl_xor_sync(0xffffffffu, v, o);
    return v;
}
__device__ __forceinline__ float sgn(float x) {
    return (x > 0.f) ? 1.f : ((x < 0.f) ? -1.f : 0.f);
}
__device__ __forceinline__ void red4(float* p, float4 o) {
    asm volatile("red.global.add.v4.f32 [%0], {%1,%2,%3,%4};"
                 :: "l"(p), "f"(o.x), "f"(o.y), "f"(o.z), "f"(o.w) : "memory");
}

// ---------------- kernels ----------------

// feats = concat(A, Bf); outb = feats * xi (layer-0 term is RAW, un-normalized)
__global__ void k_init(const float* __restrict__ A, const float* __restrict__ Bf,
                       int nA, int n, float* feats, float* outb) {
    int i = blockIdx.x * blockDim.x + threadIdx.x;
    if (i >= n * D) return;
    float v = (i < nA * D) ? A[i] : Bf[i - nA * D];
    feats[i] = v;
    outb[i]  = v * XI;
}

// out[rows[e]] += vals[e] * x[cols[e]]
// 16 threads per edge-chunk position, 4 edges per thread (MLP=4).
// Warp = 2 groups -> each LDG.128 instruction covers exactly 2 rows x 256B
// contiguous = 4 cache lines (minimal wavefronts), same for RED.
__global__ void k_spmm(const int* __restrict__ rows, const int* __restrict__ cols,
                       const float* __restrict__ vals, const float* __restrict__ x,
                       float* out, int nE) {
    int t = blockIdx.x * blockDim.x + threadIdx.x;
    int g = t >> 4;            // group of 4 consecutive edges
    int c = t & 15;            // float4 chunk within the 64-float row
    int e0 = g * 4;
    if (e0 >= nE) return;
    int nv = nE - e0;          // valid edges in this group (>=1)

    int   r[4], cc[4];
    float v[4];
#pragma unroll
    for (int k = 0; k < 4; ++k) {
        int e = e0 + ((k < nv) ? k : (nv - 1));   // clamp tail (REDs guarded below)
        r[k]  = __ldg(rows + e);
        cc[k] = __ldg(cols + e);
        v[k]  = __ldg(vals + e);
    }
    float4 a[4];
#pragma unroll
    for (int k = 0; k < 4; ++k)
        a[k] = __ldg((const float4*)(x + (size_t)cc[k] * D) + c);
#pragma unroll
    for (int k = 0; k < 4; ++k) {
        if (k < nv) {
            red4(out + (size_t)r[k] * D + c * 4,
                 make_float4(v[k]*a[k].x, v[k]*a[k].y, v[k]*a[k].z, v[k]*a[k].w));
        }
    }
}

// per-row: f = tmp + sign(tmp)*l2norm(noise)*ups ; outb += xi*l2norm(f) ; feats = f
__global__ void k_prop_row(const float* __restrict__ tmp, const float* __restrict__ noise,
                           float* feats, float* outb, int n, float ups) {
    int row = blockIdx.x * 8 + (threadIdx.x >> 5);
    int lane = threadIdx.x & 31;
    if (row >= n) return;
    size_t off = (size_t)row * D + lane * 2;
    float2 t  = *(const float2*)(tmp + off);
    float2 nz = *(const float2*)(noise + off);
    float ns = warp_sum(nz.x * nz.x + nz.y * nz.y);
    float ninv = ups / fmaxf(sqrtf(ns), 1e-12f);
    float fx = t.x + sgn(t.x) * nz.x * ninv;
    float fy = t.y + sgn(t.y) * nz.y * ninv;
    float fs = warp_sum(fx * fx + fy * fy);
    float finv = XI / fmaxf(sqrtf(fs), 1e-12f);
    float2 ob = *(float2*)(outb + off);
    ob.x += fx * finv;
    ob.y += fy * finv;
    *(float2*)(outb + off) = ob;
    *(float2*)(feats + off) = make_float2(fx, fy);
}

// aggregate: out = agg + sign(agg)*l2norm(noise)*ups (no normalize, overwrite)
__global__ void k_agg_row(const float* __restrict__ tmp, const float* __restrict__ noise,
                          float* outb, int n, float ups) {
    int row = blockIdx.x * 8 + (threadIdx.x >> 5);
    int lane = threadIdx.x & 31;
    if (row >= n) return;
    size_t off = (size_t)row * D + lane * 2;
    float2 t  = *(const float2*)(tmp + off);
    float2 nz = *(const float2*)(noise + off);
    float ns = warp_sum(nz.x * nz.x + nz.y * nz.y);
    float ninv = ups / fmaxf(sqrtf(ns), 1e-12f);
    float fx = t.x + sgn(t.x) * nz.x * ninv;
    float fy = t.y + sgn(t.y) * nz.y * ninv;
    *(float2*)(outb + off) = make_float2(fx, fy);
}

__global__ void k_sumsq(const float* __restrict__ x, int n, float* acc) {
    float s = 0.f;
    for (int i = blockIdx.x * blockDim.x + threadIdx.x; i < n; i += gridDim.x * blockDim.x) {
        float v = x[i];
        s += v * v;
    }
    s = warp_sum(s);
    __shared__ float sm[8];
    if ((threadIdx.x & 31) == 0) sm[threadIdx.x >> 5] = s;
    __syncthreads();
    if (threadIdx.x == 0) {
        float tt = 0.f;
#pragma unroll
        for (int i = 0; i < 8; ++i) tt += sm[i];
        atomicAdd(acc, tt);
    }
}

// BPR: warp per batch row; reps built on the fly
__global__ void k_bpr(const int* __restrict__ users, const int* __restrict__ bundles,
                      const float* __restrict__ UIu, const float* __restrict__ BIu,
                      const float* __restrict__ UIb, const float* __restrict__ BIb,
                      float* acc) {
    int i = blockIdx.x * 8 + (threadIdx.x >> 5);
    int lane = threadIdx.x & 31;
    if (i >= BATCH) return;
    int u  = users[i];
    int bp = bundles[2 * i];
    int bn = bundles[2 * i + 1];
    size_t uo = (size_t)u * D + lane * 2;
    float2 a1 = *(const float2*)(UIu + uo);
    float2 a2 = *(const float2*)(BIu + uo);
    float ux = 0.5f * (a1.x + a2.x), uy = 0.5f * (a1.y + a2.y);
    size_t po = (size_t)bp * D + lane * 2;
    float2 p1 = *(const float2*)(UIb + po);
    float2 p2 = *(const float2*)(BIb + po);
    float px = 0.5f * (p1.x + p2.x), py = 0.5f * (p1.y + p2.y);
    size_t no = (size_t)bn * D + lane * 2;
    float2 q1 = *(const float2*)(UIb + no);
    float2 q2 = *(const float2*)(BIb + no);
    float qx = 0.5f * (q1.x + q2.x), qy = 0.5f * (q1.y + q2.y);
    float dp = warp_sum(ux * px + uy * py);
    float dn = warp_sum(ux * qx + uy * qy);
    if (lane == 0) {
        float x = dp - dn;
        float ls = (x >= 0.f) ? -log1pf(expf(-x)) : (x - log1pf(expf(x)));
        atomicAdd(acc, ls);
    }
}

// gather + row-normalize the 6 CL matrices into k-major layout g_P[p][k][i]
__global__ void k_gather(const int* __restrict__ users, const int* __restrict__ bundles,
                         const float* __restrict__ UB, const float* __restrict__ UI,
                         const float* __restrict__ BIu, const float* __restrict__ UIb,
                         const float* __restrict__ BI, float* P) {
    int i = blockIdx.x * 8 + (threadIdx.x >> 5);
    int lane = threadIdx.x & 31;
    int p = blockIdx.y;
    if (i >= BATCH) return;
    int u0 = users[i];
    int b0 = bundles[2 * i];
    const float* src;
    switch (p) {
        case 0:  src = UB  + (size_t)u0 * D; break;
        case 1:  src = UI  + (size_t)u0 * D; break;
        case 2:  src = BIu + (size_t)u0 * D; break;
        case 3:  src = UB  + (size_t)(U_N + b0) * D; break;
        case 4:  src = UIb + (size_t)b0 * D; break;
        default: src = BI  + (size_t)b0 * D; break;
    }
    float2 v = *(const float2*)(src + lane * 2);
    float s = warp_sum(v.x * v.x + v.y * v.y);
    float inv = 1.f / fmaxf(sqrtf(s), 1e-12f);
    float* dst = P + ((size_t)p * D) * BATCH + i;
    dst[(size_t)(2 * lane) * BATCH]     = v.x * inv;
    dst[(size_t)(2 * lane + 1) * BATCH] = v.y * inv;
}

// 12 contrastive losses: S = P@Q^T/tau (2048x2048, K=64), loss_i = log(sum_j exp(S_ij)) - S_ii
// tile: 64 i-rows x 128 j-rows, 256 threads, per-thread 4x8 register tile, k-major smem.
__global__ void __launch_bounds__(256) k_cl(const float* __restrict__ P, float* acc) {
    __shared__ float Ps[64 * 64];    // [k][i] 16KB
    __shared__ float Qs[64 * 128];   // [k][j] 32KB
    int p  = blockIdx.y;
    int bi = blockIdx.x;
    int tid = threadIdx.x;
    int tx = tid & 15;     // j sub-tile (8 cols each)
    int ty = tid >> 4;     // i sub-tile (4 rows each)
    const float* Pg = P + (size_t)c_pa[p] * D * BATCH;
    const float* Qg = P + (size_t)c_pb[p] * D * BATCH;
    for (int idx = tid; idx < 64 * 16; idx += 256) {
        int k = idx >> 4, c4 = idx & 15;
        *(float4*)(Ps + k * 64 + c4 * 4) = *(const float4*)(Pg + (size_t)k * BATCH + bi * 64 + c4 * 4);
    }
    float rs[4] = {0.f, 0.f, 0.f, 0.f};
    float sii[4] = {0.f, 0.f, 0.f, 0.f};
    int ibase = bi * 64 + ty * 4;
    for (int jt = 0; jt < 16; ++jt) {
        __syncthreads();
        for (int idx = tid; idx < 64 * 32; idx += 256) {
            int k = idx >> 5, c4 = idx & 31;
            *(float4*)(Qs + k * 128 + c4 * 4) = *(const float4*)(Qg + (size_t)k * BATCH + jt * 128 + c4 * 4);
        }
        __syncthreads();
        float av[4][8];
#pragma unroll
        for (int r = 0; r < 4; ++r)
#pragma unroll
            for (int c = 0; c < 8; ++c) av[r][c] = 0.f;
#pragma unroll 8
        for (int k = 0; k < 64; ++k) {
            float a[4], b[8];
            *(float4*)a       = *(const float4*)(Ps + k * 64 + ty * 4);
            *(float4*)b       = *(const float4*)(Qs + k * 128 + tx * 8);
            *(float4*)(b + 4) = *(const float4*)(Qs + k * 128 + tx * 8 + 4);
#pragma unroll
            for (int r = 0; r < 4; ++r)
#pragma unroll
                for (int c = 0; c < 8; ++c) av[r][c] += a[r] * b[c];
        }
        int jbase = jt * 128 + tx * 8;
#pragma unroll
        for (int r = 0; r < 4; ++r) {
#pragma unroll
            for (int c = 0; c < 8; ++c) {
                float s = av[r][c] * INVTAU;
                if (jbase + c == ibase + r) sii[r] = s;
                rs[r] += __expf(s);
            }
        }
    }
    // reduce row-sums across tx (lanes share ty within 16-lane half-warps)
#pragma unroll
    for (int r = 0; r < 4; ++r)
#pragma unroll
        for (int o = 1; o < 16; o <<= 1) rs[r] += __shfl_xor_sync(0xffffffffu, rs[r], o);
    // fetch each row's diagonal from the lane that computed it
    float part = 0.f;
#pragma unroll
    for (int r = 0; r < 4; ++r) {
        int ig = ibase + r;
        int tx_d = (ig & 127) >> 3;
        int srcLane = ((ty & 1) << 4) | tx_d;
        float s = __shfl_sync(0xffffffffu, sii[r], srcLane);
        if (tx == 0) part += logf(rs[r]) - s;
    }
    if (tx == 0) atomicAdd(acc, (LAM1 * 0.5f / (float)BATCH) * part);
}

__global__ void k_final(const float* __restrict__ acc, float* out, int out_size) {
    if (threadIdx.x == 0) {
        out[0] = -acc[0] / (float)BATCH + LAM2 * acc[1];
        if (out_size > 1) out[1] = acc[2];
    }
}

// ---------------- host orchestration ----------------
extern "C" void kernel_launch(void* const* d_in, const int* in_sizes, int n_in,
                              void* d_out, int out_size) {
    const float* uf  = (const float*)d_in[0];
    const float* bfe = (const float*)d_in[1];
    const float* itf = (const float*)d_in[2];
    const int*   ub_r = (const int*)d_in[3];
    const int*   ub_c = (const int*)d_in[4];
    const float* ub_v = (const float*)d_in[5];
    const int*   ui_r = (const int*)d_in[6];
    const int*   ui_c = (const int*)d_in[7];
    const float* ui_v = (const float*)d_in[8];
    const int*   bi_r = (const int*)d_in[9];
    const int*   bi_c = (const int*)d_in[10];
    const float* bi_v = (const float*)d_in[11];
    const int*   ba_r = (const int*)d_in[12];
    const int*   ba_c = (const int*)d_in[13];
    const float* ba_v = (const float*)d_in[14];
    const int*   ua_r = (const int*)d_in[15];
    const int*   ua_c = (const int*)d_in[16];
    const float* ua_v = (const float*)d_in[17];
    const float* n_UB  = (const float*)d_in[18];
    const float* n_UI  = (const float*)d_in[19];
    const float* n_BI  = (const float*)d_in[20];
    const float* n_aBI = (const float*)d_in[21];
    const float* n_aUI = (const float*)d_in[22];
    const int* users   = (const int*)d_in[23];
    const int* bundles = (const int*)d_in[24];

    int nUB = in_sizes[3];
    int nUI = in_sizes[6];
    int nBI = in_sizes[9];
    int nBA = in_sizes[12];
    int nUA = in_sizes[15];

    float *feats, *tmp, *pUB, *pUI, *pBI, *pUIb, *pBIu, *pP, *acc;
    cudaGetSymbolAddress((void**)&feats, g_feats);
    cudaGetSymbolAddress((void**)&tmp,   g_tmp);
    cudaGetSymbolAddress((void**)&pUB,   g_UB);
    cudaGetSymbolAddress((void**)&pUI,   g_UI);
    cudaGetSymbolAddress((void**)&pBI,   g_BI);
    cudaGetSymbolAddress((void**)&pUIb,  g_UIb);
    cudaGetSymbolAddress((void**)&pBIu,  g_BIu);
    cudaGetSymbolAddress((void**)&pP,    g_P);
    cudaGetSymbolAddress((void**)&acc,   g_acc);

    cudaMemsetAsync(acc, 0, 4 * sizeof(float), 0);

    auto spmm = [&](const int* r, const int* c, const float* v, int nE,
                    const float* x, float* out) {
        long long thr = (long long)((nE + 3) / 4) * 16;
        int blocks = (int)((thr + 255) / 256);
        k_spmm<<<blocks, 256>>>(r, c, v, x, out, nE);
    };

    auto propagate = [&](const int* r, const int* c, const float* v, int nE,
                         const float* A, const float* Bf, int nA, int n,
                         const float* noise, float ups, float* outb) {
        int nd = n * D;
        k_init<<<(nd + 255) / 256, 256>>>(A, Bf, nA, n, feats, outb);
        for (int l = 0; l < 2; ++l) {
            cudaMemsetAsync(tmp, 0, (size_t)nd * sizeof(float), 0);
            spmm(r, c, v, nE, feats, tmp);
            k_prop_row<<<(n + 7) / 8, 256>>>(tmp, noise + (size_t)l * nd, feats, outb, n, ups);
        }
    };

    propagate(ub_r, ub_c, ub_v, nUB, uf,  bfe, U_N, U_N + B_N, n_UB, 0.1f, pUB);
    propagate(ui_r, ui_c, ui_v, nUI, uf,  itf, U_N, U_N + I_N, n_UI, 0.1f, pUI);
    propagate(bi_r, bi_c, bi_v, nBI, bfe, itf, B_N, B_N + I_N, n_BI, 0.1f, pBI);

    // UI_b = aggregate(biagg, UI_i)  -> B rows
    {
        cudaMemsetAsync(tmp, 0, (size_t)B_N * D * sizeof(float), 0);
        spmm(ba_r, ba_c, ba_v, nBA, pUI + (size_t)U_N * D, tmp);
        k_agg_row<<<(B_N + 7) / 8, 256>>>(tmp, n_aBI, pUIb, B_N, 0.1f);
    }
    // BI_u = aggregate(uiagg, BI_i)  -> U rows
    {
        cudaMemsetAsync(tmp, 0, (size_t)U_N * D * sizeof(float), 0);
        spmm(ua_r, ua_c, ua_v, nUA, pBI + (size_t)B_N * D, tmp);
        k_agg_row<<<(U_N + 7) / 8, 256>>>(tmp, n_aUI, pBIu, U_N, 0.1f);
    }

    // regularizer
    k_sumsq<<<592, 256>>>(uf,  U_N * D, acc + 1);
    k_sumsq<<<592, 256>>>(bfe, B_N * D, acc + 1);
    k_sumsq<<<592, 256>>>(itf, I_N * D, acc + 1);

    // BPR
    k_bpr<<<(BATCH + 7) / 8, 256>>>(users, bundles, pUI, pBIu, pUIb, pBI, acc);

    // CL matrices + losses
    dim3 gg((BATCH + 7) / 8, 6);
    k_gather<<<gg, 256>>>(users, bundles, pUB, pUI, pBIu, pUIb, pBI, pP);
    k_cl<<<dim3(32, 12), 256>>>(pP, acc + 2);

    k_final<<<1, 1>>>(acc, (float*)d_out, out_size);
}

// round 4
// speedup vs baseline: 1.3398x; 1.0056x over previous
#include <cuda_runtime.h>
#include <math.h>

#define U_N 50000
#define B_N 20000
#define I_N 100000
#define D 64
#define BATCH 2048
#define INVTAU 4.0f
#define LAM1 0.04f
#define LAM2 1e-5f
#define XI (1.0f/3.0f)

// ---------------- static device workspace (no allocs allowed) ----------------
__device__ float g_feats[(U_N + I_N) * D];   // max n = U+I = 150000
__device__ float g_tmp  [(U_N + I_N) * D];
__device__ float g_UB   [(U_N + B_N) * D];
__device__ float g_UI   [(U_N + I_N) * D];
__device__ float g_BI   [(B_N + I_N) * D];
__device__ float g_UIb  [B_N * D];           // aggregated UI_b
__device__ float g_BIu  [U_N * D];           // aggregated BI_u
__device__ float g_P    [6 * D * BATCH];     // normalized CL matrices, k-major: [p][k][i]
__device__ float g_acc  [4];                 // 0: sum logsigmoid, 1: reg, 2: cl

__constant__ int c_pa[12] = {0,0,1,3,3,4, 0,1,2,3,4,5};
__constant__ int c_pb[12] = {1,2,2,4,5,5, 0,1,2,3,4,5};

// ---------------- small helpers ----------------
__device__ __forceinline__ float warp_sum(float v) {
#pragma unroll
    for (int o = 16; o; o >>= 1) v += __shfl_xor_sync(0xffffffffu, v, o);
    return v;
}
__device__ __forceinline__ float sgn(float x) {
    return (x > 0.f) ? 1.f : ((x < 0.f) ? -1.f : 0.f);
}
__device__ __forceinline__ void red4(float* p, float4 o) {
    asm volatile("red.global.add.v4.f32 [%0], {%1,%2,%3,%4};"
                 :: "l"(p), "f"(o.x), "f"(o.y), "f"(o.z), "f"(o.w) : "memory");
}

// ---------------- kernels ----------------

// feats = concat(A, Bf); outb = feats * xi (layer-0 term is RAW, un-normalized)
__global__ void k_init(const float* __restrict__ A, const float* __restrict__ Bf,
                       int nA, int n, float* feats, float* outb) {
    int i = blockIdx.x * blockDim.x + threadIdx.x;
    if (i >= n * D) return;
    float v = (i < nA * D) ? A[i] : Bf[i - nA * D];
    feats[i] = v;
    outb[i]  = v * XI;
}

// out[rows[e]] += vals[e] * x[cols[e]]
// 16 threads per chunk position, 4 edges per thread (MLP=4), vectorized
// int4/float4 index loads (e0 is a multiple of 4 -> 16B aligned).
// Each LDG.128 / RED.128 instruction covers exactly 2 rows x 256B contiguous
// across the warp = minimal wavefronts.
__global__ void k_spmm(const int* __restrict__ rows, const int* __restrict__ cols,
                       const float* __restrict__ vals, const float* __restrict__ x,
                       float* out, int nE) {
    int t = blockIdx.x * blockDim.x + threadIdx.x;
    int g = t >> 4;            // group of 4 consecutive edges
    int c = t & 15;            // float4 chunk within the 64-float row
    int e0 = g * 4;
    if (e0 >= nE) return;
    int nv = nE - e0;          // valid edges in this group

    int   r[4], cc[4];
    float v[4];
    if (nv >= 4) {
        int4   r4 = __ldg((const int4*)(rows + e0));
        int4   c4 = __ldg((const int4*)(cols + e0));
        float4 v4 = __ldg((const float4*)(vals + e0));
        r[0]=r4.x; r[1]=r4.y; r[2]=r4.z; r[3]=r4.w;
        cc[0]=c4.x; cc[1]=c4.y; cc[2]=c4.z; cc[3]=c4.w;
        v[0]=v4.x; v[1]=v4.y; v[2]=v4.z; v[3]=v4.w;
    } else {
#pragma unroll
        for (int k = 0; k < 4; ++k) {
            int e = e0 + ((k < nv) ? k : (nv - 1));
            r[k]  = __ldg(rows + e);
            cc[k] = __ldg(cols + e);
            v[k]  = __ldg(vals + e);
        }
    }
    float4 a[4];
#pragma unroll
    for (int k = 0; k < 4; ++k)
        a[k] = __ldg((const float4*)(x + (size_t)cc[k] * D) + c);
#pragma unroll
    for (int k = 0; k < 4; ++k) {
        if (k < nv) {
            red4(out + (size_t)r[k] * D + c * 4,
                 make_float4(v[k]*a[k].x, v[k]*a[k].y, v[k]*a[k].z, v[k]*a[k].w));
        }
    }
}

// per-row: f = tmp + sign(tmp)*l2norm(noise)*ups ; outb += xi*l2norm(f) ; feats = f
__global__ void k_prop_row(const float* __restrict__ tmp, const float* __restrict__ noise,
                           float* feats, float* outb, int n, float ups) {
    int row = blockIdx.x * 8 + (threadIdx.x >> 5);
    int lane = threadIdx.x & 31;
    if (row >= n) return;
    size_t off = (size_t)row * D + lane * 2;
    float2 t  = *(const float2*)(tmp + off);
    float2 nz = *(const float2*)(noise + off);
    float ns = warp_sum(nz.x * nz.x + nz.y * nz.y);
    float ninv = ups / fmaxf(sqrtf(ns), 1e-12f);
    float fx = t.x + sgn(t.x) * nz.x * ninv;
    float fy = t.y + sgn(t.y) * nz.y * ninv;
    float fs = warp_sum(fx * fx + fy * fy);
    float finv = XI / fmaxf(sqrtf(fs), 1e-12f);
    float2 ob = *(float2*)(outb + off);
    ob.x += fx * finv;
    ob.y += fy * finv;
    *(float2*)(outb + off) = ob;
    *(float2*)(feats + off) = make_float2(fx, fy);
}

// aggregate: out = agg + sign(agg)*l2norm(noise)*ups (no normalize, overwrite)
__global__ void k_agg_row(const float* __restrict__ tmp, const float* __restrict__ noise,
                          float* outb, int n, float ups) {
    int row = blockIdx.x * 8 + (threadIdx.x >> 5);
    int lane = threadIdx.x & 31;
    if (row >= n) return;
    size_t off = (size_t)row * D + lane * 2;
    float2 t  = *(const float2*)(tmp + off);
    float2 nz = *(const float2*)(noise + off);
    float ns = warp_sum(nz.x * nz.x + nz.y * nz.y);
    float ninv = ups / fmaxf(sqrtf(ns), 1e-12f);
    float fx = t.x + sgn(t.x) * nz.x * ninv;
    float fy = t.y + sgn(t.y) * nz.y * ninv;
    *(float2*)(outb + off) = make_float2(fx, fy);
}

__global__ void k_sumsq(const float* __restrict__ x, int n, float* acc) {
    float s = 0.f;
    for (int i = blockIdx.x * blockDim.x + threadIdx.x; i < n; i += gridDim.x * blockDim.x) {
        float v = x[i];
        s += v * v;
    }
    s = warp_sum(s);
    __shared__ float sm[8];
    if ((threadIdx.x & 31) == 0) sm[threadIdx.x >> 5] = s;
    __syncthreads();
    if (threadIdx.x == 0) {
        float tt = 0.f;
#pragma unroll
        for (int i = 0; i < 8; ++i) tt += sm[i];
        atomicAdd(acc, tt);
    }
}

// BPR: warp per batch row; reps built on the fly
__global__ void k_bpr(const int* __restrict__ users, const int* __restrict__ bundles,
                      const float* __restrict__ UIu, const float* __restrict__ BIu,
                      const float* __restrict__ UIb, const float* __restrict__ BIb,
                      float* acc) {
    int i = blockIdx.x * 8 + (threadIdx.x >> 5);
    int lane = threadIdx.x & 31;
    if (i >= BATCH) return;
    int u  = users[i];
    int bp = bundles[2 * i];
    int bn = bundles[2 * i + 1];
    size_t uo = (size_t)u * D + lane * 2;
    float2 a1 = *(const float2*)(UIu + uo);
    float2 a2 = *(const float2*)(BIu + uo);
    float ux = 0.5f * (a1.x + a2.x), uy = 0.5f * (a1.y + a2.y);
    size_t po = (size_t)bp * D + lane * 2;
    float2 p1 = *(const float2*)(UIb + po);
    float2 p2 = *(const float2*)(BIb + po);
    float px = 0.5f * (p1.x + p2.x), py = 0.5f * (p1.y + p2.y);
    size_t no = (size_t)bn * D + lane * 2;
    float2 q1 = *(const float2*)(UIb + no);
    float2 q2 = *(const float2*)(BIb + no);
    float qx = 0.5f * (q1.x + q2.x), qy = 0.5f * (q1.y + q2.y);
    float dp = warp_sum(ux * px + uy * py);
    float dn = warp_sum(ux * qx + uy * qy);
    if (lane == 0) {
        float x = dp - dn;
        float ls = (x >= 0.f) ? -log1pf(expf(-x)) : (x - log1pf(expf(x)));
        atomicAdd(acc, ls);
    }
}

// gather + row-normalize the 6 CL matrices into k-major layout g_P[p][k][i]
__global__ void k_gather(const int* __restrict__ users, const int* __restrict__ bundles,
                         const float* __restrict__ UB, const float* __restrict__ UI,
                         const float* __restrict__ BIu, const float* __restrict__ UIb,
                         const float* __restrict__ BI, float* P) {
    int i = blockIdx.x * 8 + (threadIdx.x >> 5);
    int lane = threadIdx.x & 31;
    int p = blockIdx.y;
    if (i >= BATCH) return;
    int u0 = users[i];
    int b0 = bundles[2 * i];
    const float* src;
    switch (p) {
        case 0:  src = UB  + (size_t)u0 * D; break;
        case 1:  src = UI  + (size_t)u0 * D; break;
        case 2:  src = BIu + (size_t)u0 * D; break;
        case 3:  src = UB  + (size_t)(U_N + b0) * D; break;
        case 4:  src = UIb + (size_t)b0 * D; break;
        default: src = BI  + (size_t)b0 * D; break;
    }
    float2 v = *(const float2*)(src + lane * 2);
    float s = warp_sum(v.x * v.x + v.y * v.y);
    float inv = 1.f / fmaxf(sqrtf(s), 1e-12f);
    float* dst = P + ((size_t)p * D) * BATCH + i;
    dst[(size_t)(2 * lane) * BATCH]     = v.x * inv;
    dst[(size_t)(2 * lane + 1) * BATCH] = v.y * inv;
}

// 12 contrastive losses: S = P@Q^T/tau (2048x2048, K=64), loss_i = log(sum_j exp(S_ij)) - S_ii
// tile: 64 i-rows x 128 j-rows, 256 threads, per-thread 4x8 register tile, k-major smem.
__global__ void __launch_bounds__(256) k_cl(const float* __restrict__ P, float* acc) {
    __shared__ float Ps[64 * 64];    // [k][i] 16KB
    __shared__ float Qs[64 * 128];   // [k][j] 32KB
    int p  = blockIdx.y;
    int bi = blockIdx.x;
    int tid = threadIdx.x;
    int tx = tid & 15;     // j sub-tile (8 cols each)
    int ty = tid >> 4;     // i sub-tile (4 rows each)
    const float* Pg = P + (size_t)c_pa[p] * D * BATCH;
    const float* Qg = P + (size_t)c_pb[p] * D * BATCH;
    for (int idx = tid; idx < 64 * 16; idx += 256) {
        int k = idx >> 4, c4 = idx & 15;
        *(float4*)(Ps + k * 64 + c4 * 4) = *(const float4*)(Pg + (size_t)k * BATCH + bi * 64 + c4 * 4);
    }
    float rs[4] = {0.f, 0.f, 0.f, 0.f};
    float sii[4] = {0.f, 0.f, 0.f, 0.f};
    int ibase = bi * 64 + ty * 4;
    for (int jt = 0; jt < 16; ++jt) {
        __syncthreads();
        for (int idx = tid; idx < 64 * 32; idx += 256) {
            int k = idx >> 5, c4 = idx & 31;
            *(float4*)(Qs + k * 128 + c4 * 4) = *(const float4*)(Qg + (size_t)k * BATCH + jt * 128 + c4 * 4);
        }
        __syncthreads();
        float av[4][8];
#pragma unroll
        for (int r = 0; r < 4; ++r)
#pragma unroll
            for (int c = 0; c < 8; ++c) av[r][c] = 0.f;
#pragma unroll 8
        for (int k = 0; k < 64; ++k) {
            float a[4], b[8];
            *(float4*)a       = *(const float4*)(Ps + k * 64 + ty * 4);
            *(float4*)b       = *(const float4*)(Qs + k * 128 + tx * 8);
            *(float4*)(b + 4) = *(const float4*)(Qs + k * 128 + tx * 8 + 4);
#pragma unroll
            for (int r = 0; r < 4; ++r)
#pragma unroll
                for (int c = 0; c < 8; ++c) av[r][c] += a[r] * b[c];
        }
        int jbase = jt * 128 + tx * 8;
#pragma unroll
        for (int r = 0; r < 4; ++r) {
#pragma unroll
            for (int c = 0; c < 8; ++c) {
                float s = av[r][c] * INVTAU;
                if (jbase + c == ibase + r) sii[r] = s;
                rs[r] += __expf(s);
            }
        }
    }
    // reduce row-sums across tx (lanes share ty within 16-lane half-warps)
#pragma unroll
    for (int r = 0; r < 4; ++r)
#pragma unroll
        for (int o = 1; o < 16; o <<= 1) rs[r] += __shfl_xor_sync(0xffffffffu, rs[r], o);
    // fetch each row's diagonal from the lane that computed it
    float part = 0.f;
#pragma unroll
    for (int r = 0; r < 4; ++r) {
        int ig = ibase + r;
        int tx_d = (ig & 127) >> 3;
        int srcLane = ((ty & 1) << 4) | tx_d;
        float s = __shfl_sync(0xffffffffu, sii[r], srcLane);
        if (tx == 0) part += logf(rs[r]) - s;
    }
    if (tx == 0) atomicAdd(acc, (LAM1 * 0.5f / (float)BATCH) * part);
}

__global__ void k_final(const float* __restrict__ acc, float* out, int out_size) {
    if (threadIdx.x == 0) {
        out[0] = -acc[0] / (float)BATCH + LAM2 * acc[1];
        if (out_size > 1) out[1] = acc[2];
    }
}

// ---------------- host orchestration ----------------
extern "C" void kernel_launch(void* const* d_in, const int* in_sizes, int n_in,
                              void* d_out, int out_size) {
    const float* uf  = (const float*)d_in[0];
    const float* bfe = (const float*)d_in[1];
    const float* itf = (const float*)d_in[2];
    const int*   ub_r = (const int*)d_in[3];
    const int*   ub_c = (const int*)d_in[4];
    const float* ub_v = (const float*)d_in[5];
    const int*   ui_r = (const int*)d_in[6];
    const int*   ui_c = (const int*)d_in[7];
    const float* ui_v = (const float*)d_in[8];
    const int*   bi_r = (const int*)d_in[9];
    const int*   bi_c = (const int*)d_in[10];
    const float* bi_v = (const float*)d_in[11];
    const int*   ba_r = (const int*)d_in[12];
    const int*   ba_c = (const int*)d_in[13];
    const float* ba_v = (const float*)d_in[14];
    const int*   ua_r = (const int*)d_in[15];
    const int*   ua_c = (const int*)d_in[16];
    const float* ua_v = (const float*)d_in[17];
    const float* n_UB  = (const float*)d_in[18];
    const float* n_UI  = (const float*)d_in[19];
    const float* n_BI  = (const float*)d_in[20];
    const float* n_aBI = (const float*)d_in[21];
    const float* n_aUI = (const float*)d_in[22];
    const int* users   = (const int*)d_in[23];
    const int* bundles = (const int*)d_in[24];

    int nUB = in_sizes[3];
    int nUI = in_sizes[6];
    int nBI = in_sizes[9];
    int nBA = in_sizes[12];
    int nUA = in_sizes[15];

    float *feats, *tmp, *pUB, *pUI, *pBI, *pUIb, *pBIu, *pP, *acc;
    cudaGetSymbolAddress((void**)&feats, g_feats);
    cudaGetSymbolAddress((void**)&tmp,   g_tmp);
    cudaGetSymbolAddress((void**)&pUB,   g_UB);
    cudaGetSymbolAddress((void**)&pUI,   g_UI);
    cudaGetSymbolAddress((void**)&pBI,   g_BI);
    cudaGetSymbolAddress((void**)&pUIb,  g_UIb);
    cudaGetSymbolAddress((void**)&pBIu,  g_BIu);
    cudaGetSymbolAddress((void**)&pP,    g_P);
    cudaGetSymbolAddress((void**)&acc,   g_acc);

    cudaMemsetAsync(acc, 0, 4 * sizeof(float), 0);

    auto spmm = [&](const int* r, const int* c, const float* v, int nE,
                    const float* x, float* out) {
        long long thr = (long long)((nE + 3) / 4) * 16;
        int blocks = (int)((thr + 255) / 256);
        k_spmm<<<blocks, 256>>>(r, c, v, x, out, nE);
    };

    auto propagate = [&](const int* r, const int* c, const float* v, int nE,
                         const float* A, const float* Bf, int nA, int n,
                         const float* noise, float ups, float* outb) {
        int nd = n * D;
        k_init<<<(nd + 255) / 256, 256>>>(A, Bf, nA, n, feats, outb);
        for (int l = 0; l < 2; ++l) {
            cudaMemsetAsync(tmp, 0, (size_t)nd * sizeof(float), 0);
            spmm(r, c, v, nE, feats, tmp);
            k_prop_row<<<(n + 7) / 8, 256>>>(tmp, noise + (size_t)l * nd, feats, outb, n, ups);
        }
    };

    propagate(ub_r, ub_c, ub_v, nUB, uf,  bfe, U_N, U_N + B_N, n_UB, 0.1f, pUB);
    propagate(ui_r, ui_c, ui_v, nUI, uf,  itf, U_N, U_N + I_N, n_UI, 0.1f, pUI);
    propagate(bi_r, bi_c, bi_v, nBI, bfe, itf, B_N, B_N + I_N, n_BI, 0.1f, pBI);

    // UI_b = aggregate(biagg, UI_i)  -> B rows
    {
        cudaMemsetAsync(tmp, 0, (size_t)B_N * D * sizeof(float), 0);
        spmm(ba_r, ba_c, ba_v, nBA, pUI + (size_t)U_N * D, tmp);
        k_agg_row<<<(B_N + 7) / 8, 256>>>(tmp, n_aBI, pUIb, B_N, 0.1f);
    }
    // BI_u = aggregate(uiagg, BI_i)  -> U rows
    {
        cudaMemsetAsync(tmp, 0, (size_t)U_N * D * sizeof(float), 0);
        spmm(ua_r, ua_c, ua_v, nUA, pBI + (size_t)B_N * D, tmp);
        k_agg_row<<<(U_N + 7) / 8, 256>>>(tmp, n_aUI, pBIu, U_N, 0.1f);
    }

    // regularizer
    k_sumsq<<<592, 256>>>(uf,  U_N * D, acc + 1);
    k_sumsq<<<592, 256>>>(bfe, B_N * D, acc + 1);
    k_sumsq<<<592, 256>>>(itf, I_N * D, acc + 1);

    // BPR
    k_bpr<<<(BATCH + 7) / 8, 256>>>(users, bundles, pUI, pBIu, pUIb, pBI, acc);

    // CL matrices + losses
    dim3 gg((BATCH + 7) / 8, 6);
    k_gather<<<gg, 256>>>(users, bundles, pUB, pUI, pBIu, pUIb, pBI, pP);
    k_cl<<<dim3(32, 12), 256>>>(pP, acc + 2);

    k_final<<<1, 1>>>(acc, (float*)d_out, out_size);
}